// round 15
// baseline (speedup 1.0000x reference)
#include <cuda_runtime.h>
#include <cuda_fp16.h>
#include <stdint.h>
#include <math.h>

#define NN 100000
#define EE 1600000
#define NEG_SLOPE 0.2f
#define SCAN_B 1024
#define NSB ((NN + SCAN_B - 1) / SCAN_B)   // 98 scan blocks
#define CH0 50048                          // 391 * 128 (chunk boundary, GEMM-tile aligned)

// ---------------- device scratch ----------------
__device__ int   g_flag64;
__device__ int   g_deg[NN];
__device__ int   g_off[NN + 1];
__device__ int   g_scanv[NN];
__device__ int   g_bsum[NSB];
__device__ int   g_slot[EE];
__device__ __align__(16) int   g_csr_src[EE];
__device__ __align__(16) float g_csr_attr[EE];
__device__ __align__(16) float g_alpha[EE];
__device__ __align__(16) float g_h[(size_t)NN * 64];     // layer-1 features (fp32, for dots/x2 path)
__device__ __align__(16) float g_h2[(size_t)NN * 64];    // layer-2 features (fp32)
__device__ __align__(16) __half g_h16[(size_t)NN * 64];  // layer-1 fp16 gather copy
__device__ __align__(16) __half g_h216[(size_t)NN * 64]; // layer-2 fp16 gather copy
__device__ __align__(16) float g_x2[(size_t)NN * 64];    // relu(layer-1 out)
__device__ float g_ssrc[NN],  g_sdst[NN];
__device__ float g_ssrc2[NN], g_sdst2[NN];

// ---------------- dtype detect ----------------
__global__ void detect_k(const void* __restrict__ ei, int* __restrict__ flag) {
    const long long* e64 = (const long long*)ei;
    int lane = threadIdx.x;
    long long a = e64[lane];
    long long b = e64[32 + lane];
    int bad = (a < 0 || a >= NN) || (b < 0 || b >= NN);
    unsigned bal = __ballot_sync(0xffffffffu, bad);
    if (lane == 0) *flag = (bal == 0) ? 1 : 0;
}

// ---------------- histogram over dst (4 edges/thread) + slot recording ----------------
__global__ void hist_k(const void* __restrict__ ei, const int* __restrict__ flag,
                       int* __restrict__ deg, int* __restrict__ slot) {
    int e = (blockIdx.x * blockDim.x + threadIdx.x) * 4;
    if (e >= EE) return;
    int d0, d1, d2, d3;
    if (*flag) {
        const long long* p = (const long long*)ei + EE + e;
        longlong2 a = ((const longlong2*)p)[0];
        longlong2 b = ((const longlong2*)p)[1];
        d0 = (int)a.x; d1 = (int)a.y; d2 = (int)b.x; d3 = (int)b.y;
    } else {
        int4 d = *(const int4*)((const int*)ei + EE + e);
        d0 = d.x; d1 = d.y; d2 = d.z; d3 = d.w;
    }
    int4 sl;
    sl.x = atomicAdd(deg + d0, 1);
    sl.y = atomicAdd(deg + d1, 1);
    sl.z = atomicAdd(deg + d2, 1);
    sl.w = atomicAdd(deg + d3, 1);
    *(int4*)(slot + e) = sl;
}

// ---------------- scan stage 1 (self-clearing) ----------------
__global__ void scan1_k(int* __restrict__ deg,
                        int* __restrict__ scanv, int* __restrict__ bsum) {
    __shared__ int s[SCAN_B];
    int tid = threadIdx.x;
    int i = blockIdx.x * SCAN_B + tid;
    int v = (i < NN) ? deg[i] : 0;
    s[tid] = v;
    if (i < NN) deg[i] = 0;
    __syncthreads();
#pragma unroll
    for (int d = 1; d < SCAN_B; d <<= 1) {
        int t = (tid >= d) ? s[tid - d] : 0;
        __syncthreads();
        s[tid] += t;
        __syncthreads();
    }
    if (i < NN) scanv[i] = s[tid];
    if (tid == SCAN_B - 1) bsum[blockIdx.x] = s[tid];
}

// ---------------- scan stage 2+3 fused ----------------
__global__ void scan23_k(const int* __restrict__ scanv, const int* __restrict__ bsum,
                         int* __restrict__ off) {
    __shared__ int s[128];
    int tid = threadIdx.x;
    if (tid < 128) s[tid] = (tid < NSB) ? bsum[tid] : 0;
    __syncthreads();
#pragma unroll
    for (int d = 1; d < 128; d <<= 1) {
        int t = (tid >= d && tid < 128) ? s[tid - d] : 0;
        __syncthreads();
        if (tid < 128) s[tid] += t;
        __syncthreads();
    }
    int bp = (blockIdx.x == 0) ? 0 : s[blockIdx.x - 1];
    int i = blockIdx.x * SCAN_B + tid;
    if (i < NN) off[i + 1] = scanv[i] + bp;
    if (i == 0) off[0] = 0;
}

// ---------------- scatter into CSR (atomic-free) ----------------
__global__ void scatter_k(const void* __restrict__ ei, const int* __restrict__ flag,
                          const float* __restrict__ ea,
                          const int* __restrict__ off, const int* __restrict__ slot,
                          int* __restrict__ csrc, float* __restrict__ cattr) {
    int e = blockIdx.x * blockDim.x + threadIdx.x;
    if (e >= EE) return;
    int s, d;
    if (*flag) {
        const long long* p = (const long long*)ei;
        s = (int)p[e];
        d = (int)p[EE + e];
    } else {
        const int* p = (const int*)ei;
        s = p[e];
        d = p[EE + e];
    }
    int pos = off[d] + slot[e];
    csrc[pos]  = s;
    cattr[pos] = ea[e];
}

// ---------------- GEMM: h = x @ W over [rowbase, rowend) ; also fp16 copy ----------------
#define GEMM_ROWS 128
__global__ void __launch_bounds__(256, 2)
gemm64_k(const float* __restrict__ x, const float* __restrict__ W,
         float* __restrict__ h, __half* __restrict__ h16,
         int rowbase, int rowend) {
    __shared__ float4 xs[16][16];

    int tid = threadIdx.x;
    int d   = tid & 63;
    int y   = tid >> 6;

    float w[64];
#pragma unroll
    for (int k = 0; k < 64; ++k) w[k] = W[k * 64 + d];

    int row0 = rowbase + blockIdx.x * GEMM_ROWS;
#pragma unroll 1
    for (int t = 0; t < GEMM_ROWS / 16; ++t) {
        int rbase = row0 + t * 16;
        {
            int rr = rbase + (tid >> 4);
            float4 val = make_float4(0.f, 0.f, 0.f, 0.f);
            if (rr < rowend) val = ((const float4*)x)[(size_t)rr * 16 + (tid & 15)];
            xs[tid >> 4][tid & 15] = val;
        }
        __syncthreads();

        float acc0 = 0.f, acc1 = 0.f, acc2 = 0.f, acc3 = 0.f;
#pragma unroll
        for (int k4 = 0; k4 < 16; ++k4) {
            float w0 = w[4 * k4 + 0], w1 = w[4 * k4 + 1];
            float w2 = w[4 * k4 + 2], w3 = w[4 * k4 + 3];
            float4 a = xs[y * 4 + 0][k4];
            acc0 += a.x * w0 + a.y * w1 + a.z * w2 + a.w * w3;
            float4 b = xs[y * 4 + 1][k4];
            acc1 += b.x * w0 + b.y * w1 + b.z * w2 + b.w * w3;
            float4 c = xs[y * 4 + 2][k4];
            acc2 += c.x * w0 + c.y * w1 + c.z * w2 + c.w * w3;
            float4 e = xs[y * 4 + 3][k4];
            acc3 += e.x * w0 + e.y * w1 + e.z * w2 + e.w * w3;
        }
        int r0 = rbase + y * 4;
        if (r0 + 0 < rowend) { h[(size_t)(r0 + 0) * 64 + d] = acc0; h16[(size_t)(r0 + 0) * 64 + d] = __float2half(acc0); }
        if (r0 + 1 < rowend) { h[(size_t)(r0 + 1) * 64 + d] = acc1; h16[(size_t)(r0 + 1) * 64 + d] = __float2half(acc1); }
        if (r0 + 2 < rowend) { h[(size_t)(r0 + 2) * 64 + d] = acc2; h16[(size_t)(r0 + 2) * 64 + d] = __float2half(acc2); }
        if (r0 + 3 < rowend) { h[(size_t)(r0 + 3) * 64 + d] = acc3; h16[(size_t)(r0 + 3) * 64 + d] = __float2half(acc3); }
        __syncthreads();
    }
}

// ---------------- per-node attention dots over [nbase, nend) ----------------
__global__ void dots_k(const float* __restrict__ h,
                       const float* __restrict__ a_src, const float* __restrict__ a_dst,
                       float* __restrict__ ssrc, float* __restrict__ sdst,
                       int nbase, int nend) {
    int gt   = blockIdx.x * blockDim.x + threadIdx.x;
    int node = nbase + (gt >> 5);
    int lane = gt & 31;
    if (node >= nend) return;
    float h0 = h[(size_t)node * 64 + lane];
    float h1 = h[(size_t)node * 64 + 32 + lane];
    float ps = h0 * a_src[lane] + h1 * a_src[lane + 32];
    float pd = h0 * a_dst[lane] + h1 * a_dst[lane + 32];
#pragma unroll
    for (int o = 16; o; o >>= 1) {
        ps += __shfl_xor_sync(0xffffffffu, ps, o);
        pd += __shfl_xor_sync(0xffffffffu, pd, o);
    }
    if (lane == 0) { ssrc[node] = ps; sdst[node] = pd; }
}

// ---------------- warp-per-node aggregate (R12 structure; fp16 gather in pass 2) ----------------
__global__ void agg_k(const int* __restrict__ off,
                      const int* __restrict__ csrc, const float* __restrict__ cattr,
                      const __half2* __restrict__ h16,
                      const float* __restrict__ ssrc, const float* __restrict__ sdst,
                      const float* __restrict__ We, const float* __restrict__ ae,
                      const float* __restrict__ bias,
                      float* __restrict__ alpha,
                      float* __restrict__ outp, int relu_out,
                      int vbase, int vend) {
    int gt   = blockIdx.x * blockDim.x + threadIdx.x;
    int lane = gt & 31;
    int v    = vbase + (gt >> 5);
    if (v >= vend) return;

    // c = sum_d We[d]*ae[d]
    float c = We[lane] * ae[lane] + We[lane + 32] * ae[lane + 32];
#pragma unroll
    for (int o = 16; o; o >>= 1) c += __shfl_xor_sync(0xffffffffu, c, o);

    int beg = off[v];
    int end = off[v + 1];
    float sdv = sdst[v];

    // pass 1: e = exp(leakyrelu(logit)) ; store e ; accumulate sum  (identical to R12)
    float s = 0.f;
    for (int j = beg + lane; j < end; j += 32) {
        int u   = csrc[j];
        float a = ssrc[u] + sdv + cattr[j] * c;
        a = (a > 0.f) ? a : NEG_SLOPE * a;
        float e = __expf(a);
        alpha[j] = e;
        s += e;
    }
#pragma unroll
    for (int o = 16; o; o >>= 1) s += __shfl_xor_sync(0xffffffffu, s, o);
    float inv = 1.f / (s + 1e-16f);

    // pass 2: R12 loop, but gather fp16 (1 L2 line per edge instead of 2)
    float accx = 0.f, accy = 0.f;
#pragma unroll 4
    for (int j = beg; j < end; ++j) {
        int u   = csrc[j];                 // warp-broadcast (L1-resident line)
        float w = alpha[j] * inv;          // warp-broadcast
        float2 hv = __half22float2(h16[(size_t)u * 32 + lane]);
        accx += w * hv.x;
        accy += w * hv.y;
    }
    float2 b = ((const float2*)bias)[lane];
    float ox = accx + b.x;
    float oy = accy + b.y;
    if (relu_out) { ox = fmaxf(ox, 0.f); oy = fmaxf(oy, 0.f); }
    float2 o2; o2.x = ox; o2.y = oy;
    ((float2*)outp)[(size_t)v * 32 + lane] = o2;
}

// ---------------- launch ----------------
extern "C" void kernel_launch(void* const* d_in, const int* in_sizes, int n_in,
                              void* d_out, int out_size) {
    const float* x   = (const float*)d_in[0];
    const void*  ei  = d_in[1];
    const float* ea  = (const float*)d_in[2];
    const float* W1  = (const float*)d_in[3];
    const float* We1 = (const float*)d_in[4];
    const float* as1 = (const float*)d_in[5];
    const float* ad1 = (const float*)d_in[6];
    const float* ae1 = (const float*)d_in[7];
    const float* b1  = (const float*)d_in[8];
    const float* W2  = (const float*)d_in[9];
    const float* We2 = (const float*)d_in[10];
    const float* as2 = (const float*)d_in[11];
    const float* ad2 = (const float*)d_in[12];
    const float* ae2 = (const float*)d_in[13];
    const float* b2  = (const float*)d_in[14];
    float* out = (float*)d_out;

    void *p_flag, *p_deg, *p_off, *p_scanv, *p_bsum, *p_slot,
         *p_csrc, *p_cattr, *p_alpha, *p_h, *p_h2, *p_h16, *p_h216, *p_x2,
         *p_ssrc, *p_sdst, *p_ssrc2, *p_sdst2;
    cudaGetSymbolAddress(&p_flag,  g_flag64);
    cudaGetSymbolAddress(&p_deg,   g_deg);
    cudaGetSymbolAddress(&p_off,   g_off);
    cudaGetSymbolAddress(&p_scanv, g_scanv);
    cudaGetSymbolAddress(&p_bsum,  g_bsum);
    cudaGetSymbolAddress(&p_slot,  g_slot);
    cudaGetSymbolAddress(&p_csrc,  g_csr_src);
    cudaGetSymbolAddress(&p_cattr, g_csr_attr);
    cudaGetSymbolAddress(&p_alpha, g_alpha);
    cudaGetSymbolAddress(&p_h,     g_h);
    cudaGetSymbolAddress(&p_h2,    g_h2);
    cudaGetSymbolAddress(&p_h16,   g_h16);
    cudaGetSymbolAddress(&p_h216,  g_h216);
    cudaGetSymbolAddress(&p_x2,    g_x2);
    cudaGetSymbolAddress(&p_ssrc,  g_ssrc);
    cudaGetSymbolAddress(&p_sdst,  g_sdst);
    cudaGetSymbolAddress(&p_ssrc2, g_ssrc2);
    cudaGetSymbolAddress(&p_sdst2, g_sdst2);

    int*    flag  = (int*)p_flag;
    int*    deg   = (int*)p_deg;
    int*    off   = (int*)p_off;
    int*    scanv = (int*)p_scanv;
    int*    bsum  = (int*)p_bsum;
    int*    slot  = (int*)p_slot;
    int*    csrc  = (int*)p_csrc;
    float*  cattr = (float*)p_cattr;
    float*  alpha = (float*)p_alpha;
    float*  h     = (float*)p_h;
    float*  h2    = (float*)p_h2;
    __half* h16   = (__half*)p_h16;
    __half* h216  = (__half*)p_h216;
    float*  x2    = (float*)p_x2;
    float*  ssrc  = (float*)p_ssrc;
    float*  sdst  = (float*)p_sdst;
    float*  ssrc2 = (float*)p_ssrc2;
    float*  sdst2 = (float*)p_sdst2;

    const int EB  = (EE + 255) / 256;
    const int EB4 = (EE / 4 + 255) / 256;
    const int GB  = (NN + GEMM_ROWS - 1) / GEMM_ROWS;
    const int WB  = (NN * 32 + 255) / 256;

    const int CH1 = NN - CH0;
    const int GB0 = CH0 / GEMM_ROWS;
    const int GB1 = (CH1 + GEMM_ROWS - 1) / GEMM_ROWS;
    const int WB0 = CH0 / 8;
    const int WB1 = (CH1 * 32 + 255) / 256;

    static cudaStream_t s2 = nullptr;
    static cudaEvent_t evFork = nullptr, evSide = nullptr, evA = nullptr, evB = nullptr;
    if (s2 == nullptr) {
        cudaStreamCreateWithFlags(&s2, cudaStreamNonBlocking);
        cudaEventCreateWithFlags(&evFork, cudaEventDisableTiming);
        cudaEventCreateWithFlags(&evSide, cudaEventDisableTiming);
        cudaEventCreateWithFlags(&evA,    cudaEventDisableTiming);
        cudaEventCreateWithFlags(&evB,    cudaEventDisableTiming);
    }

    // fork: side stream does layer-1 GEMM + dots while main builds CSR
    cudaEventRecord(evFork, 0);
    cudaStreamWaitEvent(s2, evFork, 0);

    gemm64_k<<<GB, 256, 0, s2>>>(x, W1, h, h16, 0, NN);
    dots_k<<<WB, 256, 0, s2>>>(h, as1, ad1, ssrc, sdst, 0, NN);
    cudaEventRecord(evSide, s2);

    // main stream: CSR build
    detect_k<<<1, 32>>>(ei, flag);
    hist_k<<<EB4, 256>>>(ei, flag, deg, slot);
    scan1_k<<<NSB, SCAN_B>>>(deg, scanv, bsum);
    scan23_k<<<NSB, SCAN_B>>>(scanv, bsum, off);
    scatter_k<<<EB, 256>>>(ei, flag, ea, off, slot, csrc, cattr);

    // join layer-1 prep, then race-free chunked pipeline
    cudaStreamWaitEvent(0, evSide, 0);

    agg_k<<<WB0, 256>>>(off, csrc, cattr, (const __half2*)h16, ssrc, sdst, We1, ae1, b1, alpha, x2, 1, 0, CH0);
    cudaEventRecord(evA, 0);

    cudaStreamWaitEvent(s2, evA, 0);
    gemm64_k<<<GB0, 256, 0, s2>>>(x2, W2, h2, h216, 0, CH0);
    dots_k<<<WB0, 256, 0, s2>>>(h2, as2, ad2, ssrc2, sdst2, 0, CH0);
    cudaEventRecord(evB, s2);

    agg_k<<<WB1, 256>>>(off, csrc, cattr, (const __half2*)h16, ssrc, sdst, We1, ae1, b1, alpha, x2, 1, CH0, NN);
    gemm64_k<<<GB1, 256>>>(x2, W2, h2, h216, CH0, NN);
    dots_k<<<WB1, 256>>>(h2, as2, ad2, ssrc2, sdst2, CH0, NN);

    cudaStreamWaitEvent(0, evB, 0);
    agg_k<<<WB, 256>>>(off, csrc, cattr, (const __half2*)h216, ssrc2, sdst2, We2, ae2, b2, alpha, out, 0, 0, NN);
}

// round 16
// speedup vs baseline: 1.1126x; 1.1126x over previous
#include <cuda_runtime.h>
#include <stdint.h>
#include <math.h>

#define NN 100000
#define EE 1600000
#define NEG_SLOPE 0.2f
#define SCAN_B 1024
#define NSB ((NN + SCAN_B - 1) / SCAN_B)   // 98 scan blocks
#define CH0 50048                          // 391 * 128 (chunk boundary, GEMM-tile aligned)

// ---------------- device scratch ----------------
__device__ int   g_flag64;
__device__ int   g_deg[NN];
__device__ int   g_off[NN + 1];
__device__ int   g_scanv[NN];
__device__ int   g_bsum[NSB];
__device__ int   g_slot[EE];
__device__ __align__(16) int2  g_pair[EE];   // (src, attr-bits): ONE 8B scattered store per edge
__device__ __align__(16) float g_alpha[EE];
__device__ __align__(16) float g_h[(size_t)NN * 64];    // layer-1 features
__device__ __align__(16) float g_h2[(size_t)NN * 64];   // layer-2 features
__device__ __align__(16) float g_x2[(size_t)NN * 64];   // relu(layer-1 out)
__device__ float g_ssrc[NN],  g_sdst[NN];
__device__ float g_ssrc2[NN], g_sdst2[NN];

// ---------------- dtype detect ----------------
__global__ void detect_k(const void* __restrict__ ei, int* __restrict__ flag) {
    const long long* e64 = (const long long*)ei;
    int lane = threadIdx.x;
    long long a = e64[lane];
    long long b = e64[32 + lane];
    int bad = (a < 0 || a >= NN) || (b < 0 || b >= NN);
    unsigned bal = __ballot_sync(0xffffffffu, bad);
    if (lane == 0) *flag = (bal == 0) ? 1 : 0;
}

// ---------------- histogram over dst (4 edges/thread) + slot recording ----------------
__global__ void hist_k(const void* __restrict__ ei, const int* __restrict__ flag,
                       int* __restrict__ deg, int* __restrict__ slot) {
    int e = (blockIdx.x * blockDim.x + threadIdx.x) * 4;
    if (e >= EE) return;
    int d0, d1, d2, d3;
    if (*flag) {
        const long long* p = (const long long*)ei + EE + e;
        longlong2 a = ((const longlong2*)p)[0];
        longlong2 b = ((const longlong2*)p)[1];
        d0 = (int)a.x; d1 = (int)a.y; d2 = (int)b.x; d3 = (int)b.y;
    } else {
        int4 d = *(const int4*)((const int*)ei + EE + e);
        d0 = d.x; d1 = d.y; d2 = d.z; d3 = d.w;
    }
    int4 sl;
    sl.x = atomicAdd(deg + d0, 1);
    sl.y = atomicAdd(deg + d1, 1);
    sl.z = atomicAdd(deg + d2, 1);
    sl.w = atomicAdd(deg + d3, 1);
    *(int4*)(slot + e) = sl;
}

// ---------------- scan stage 1 (self-clearing) ----------------
__global__ void scan1_k(int* __restrict__ deg,
                        int* __restrict__ scanv, int* __restrict__ bsum) {
    __shared__ int s[SCAN_B];
    int tid = threadIdx.x;
    int i = blockIdx.x * SCAN_B + tid;
    int v = (i < NN) ? deg[i] : 0;
    s[tid] = v;
    if (i < NN) deg[i] = 0;
    __syncthreads();
#pragma unroll
    for (int d = 1; d < SCAN_B; d <<= 1) {
        int t = (tid >= d) ? s[tid - d] : 0;
        __syncthreads();
        s[tid] += t;
        __syncthreads();
    }
    if (i < NN) scanv[i] = s[tid];
    if (tid == SCAN_B - 1) bsum[blockIdx.x] = s[tid];
}

// ---------------- scan stage 2+3 fused ----------------
__global__ void scan23_k(const int* __restrict__ scanv, const int* __restrict__ bsum,
                         int* __restrict__ off) {
    __shared__ int s[128];
    int tid = threadIdx.x;
    if (tid < 128) s[tid] = (tid < NSB) ? bsum[tid] : 0;
    __syncthreads();
#pragma unroll
    for (int d = 1; d < 128; d <<= 1) {
        int t = (tid >= d && tid < 128) ? s[tid - d] : 0;
        __syncthreads();
        if (tid < 128) s[tid] += t;
        __syncthreads();
    }
    int bp = (blockIdx.x == 0) ? 0 : s[blockIdx.x - 1];
    int i = blockIdx.x * SCAN_B + tid;
    if (i < NN) off[i + 1] = scanv[i] + bp;
    if (i == 0) off[0] = 0;
}

// ---------------- scatter into packed CSR (atomic-free, ONE 8B store/edge) ----------------
__global__ void scatter_k(const void* __restrict__ ei, const int* __restrict__ flag,
                          const float* __restrict__ ea,
                          const int* __restrict__ off, const int* __restrict__ slot,
                          int2* __restrict__ pair) {
    int e = blockIdx.x * blockDim.x + threadIdx.x;
    if (e >= EE) return;
    int s, d;
    if (*flag) {
        const long long* p = (const long long*)ei;
        s = (int)p[e];
        d = (int)p[EE + e];
    } else {
        const int* p = (const int*)ei;
        s = p[e];
        d = p[EE + e];
    }
    int pos = off[d] + slot[e];
    int2 pr; pr.x = s; pr.y = __float_as_int(ea[e]);
    pair[pos] = pr;
}

// ---------------- GEMM: h = x @ W over row range [rowbase, rowend) ----------------
#define GEMM_ROWS 128
__global__ void __launch_bounds__(256, 2)
gemm64_k(const float* __restrict__ x, const float* __restrict__ W, float* __restrict__ h,
         int rowbase, int rowend) {
    __shared__ float4 xs[16][16];

    int tid = threadIdx.x;
    int d   = tid & 63;
    int y   = tid >> 6;

    float w[64];
#pragma unroll
    for (int k = 0; k < 64; ++k) w[k] = W[k * 64 + d];

    int row0 = rowbase + blockIdx.x * GEMM_ROWS;
#pragma unroll 1
    for (int t = 0; t < GEMM_ROWS / 16; ++t) {
        int rbase = row0 + t * 16;
        {
            int rr = rbase + (tid >> 4);
            float4 val = make_float4(0.f, 0.f, 0.f, 0.f);
            if (rr < rowend) val = ((const float4*)x)[(size_t)rr * 16 + (tid & 15)];
            xs[tid >> 4][tid & 15] = val;
        }
        __syncthreads();

        float acc0 = 0.f, acc1 = 0.f, acc2 = 0.f, acc3 = 0.f;
#pragma unroll
        for (int k4 = 0; k4 < 16; ++k4) {
            float w0 = w[4 * k4 + 0], w1 = w[4 * k4 + 1];
            float w2 = w[4 * k4 + 2], w3 = w[4 * k4 + 3];
            float4 a = xs[y * 4 + 0][k4];
            acc0 += a.x * w0 + a.y * w1 + a.z * w2 + a.w * w3;
            float4 b = xs[y * 4 + 1][k4];
            acc1 += b.x * w0 + b.y * w1 + b.z * w2 + b.w * w3;
            float4 c = xs[y * 4 + 2][k4];
            acc2 += c.x * w0 + c.y * w1 + c.z * w2 + c.w * w3;
            float4 e = xs[y * 4 + 3][k4];
            acc3 += e.x * w0 + e.y * w1 + e.z * w2 + e.w * w3;
        }
        int r0 = rbase + y * 4;
        if (r0 + 0 < rowend) h[(size_t)(r0 + 0) * 64 + d] = acc0;
        if (r0 + 1 < rowend) h[(size_t)(r0 + 1) * 64 + d] = acc1;
        if (r0 + 2 < rowend) h[(size_t)(r0 + 2) * 64 + d] = acc2;
        if (r0 + 3 < rowend) h[(size_t)(r0 + 3) * 64 + d] = acc3;
        __syncthreads();
    }
}

// ---------------- per-node attention dots over [nbase, nend) ----------------
__global__ void dots_k(const float* __restrict__ h,
                       const float* __restrict__ a_src, const float* __restrict__ a_dst,
                       float* __restrict__ ssrc, float* __restrict__ sdst,
                       int nbase, int nend) {
    int gt   = blockIdx.x * blockDim.x + threadIdx.x;
    int node = nbase + (gt >> 5);
    int lane = gt & 31;
    if (node >= nend) return;
    float h0 = h[(size_t)node * 64 + lane];
    float h1 = h[(size_t)node * 64 + 32 + lane];
    float ps = h0 * a_src[lane] + h1 * a_src[lane + 32];
    float pd = h0 * a_dst[lane] + h1 * a_dst[lane + 32];
#pragma unroll
    for (int o = 16; o; o >>= 1) {
        ps += __shfl_xor_sync(0xffffffffu, ps, o);
        pd += __shfl_xor_sync(0xffffffffu, pd, o);
    }
    if (lane == 0) { ssrc[node] = ps; sdst[node] = pd; }
}

// ---------------- warp-per-node aggregate (R12 loop structure, packed CSR reads) ----------------
__global__ void agg_k(const int* __restrict__ off,
                      const int2* __restrict__ pair,
                      const float* __restrict__ h,
                      const float* __restrict__ ssrc, const float* __restrict__ sdst,
                      const float* __restrict__ We, const float* __restrict__ ae,
                      const float* __restrict__ bias,
                      float* __restrict__ alpha,
                      float* __restrict__ outp, int relu_out,
                      int vbase, int vend) {
    int gt   = blockIdx.x * blockDim.x + threadIdx.x;
    int lane = gt & 31;
    int v    = vbase + (gt >> 5);
    if (v >= vend) return;

    // c = sum_d We[d]*ae[d]
    float c = We[lane] * ae[lane] + We[lane + 32] * ae[lane + 32];
#pragma unroll
    for (int o = 16; o; o >>= 1) c += __shfl_xor_sync(0xffffffffu, c, o);

    int beg = off[v];
    int end = off[v + 1];
    float sdv = sdst[v];

    // pass 1: e = exp(leakyrelu(logit)) ; store e ; accumulate sum
    float s = 0.f;
    for (int j = beg + lane; j < end; j += 32) {
        int2 pr = pair[j];
        float a = ssrc[pr.x] + sdv + __int_as_float(pr.y) * c;
        a = (a > 0.f) ? a : NEG_SLOPE * a;
        float e = __expf(a);
        alpha[j] = e;
        s += e;
    }
#pragma unroll
    for (int o = 16; o; o >>= 1) s += __shfl_xor_sync(0xffffffffu, s, o);
    float inv = 1.f / (s + 1e-16f);

    // pass 2: each lane owns 2 output channels (identical to R12)
    float accx = 0.f, accy = 0.f;
#pragma unroll 4
    for (int j = beg; j < end; ++j) {
        int u   = pair[j].x;               // warp-broadcast (uniform, amortized)
        float w = alpha[j] * inv;          // warp-broadcast
        float2 hv = ((const float2*)h)[(size_t)u * 32 + lane];
        accx += w * hv.x;
        accy += w * hv.y;
    }
    float2 b = ((const float2*)bias)[lane];
    float ox = accx + b.x;
    float oy = accy + b.y;
    if (relu_out) { ox = fmaxf(ox, 0.f); oy = fmaxf(oy, 0.f); }
    float2 o2; o2.x = ox; o2.y = oy;
    ((float2*)outp)[(size_t)v * 32 + lane] = o2;
}

// ---------------- launch ----------------
extern "C" void kernel_launch(void* const* d_in, const int* in_sizes, int n_in,
                              void* d_out, int out_size) {
    const float* x   = (const float*)d_in[0];
    const void*  ei  = d_in[1];
    const float* ea  = (const float*)d_in[2];
    const float* W1  = (const float*)d_in[3];
    const float* We1 = (const float*)d_in[4];
    const float* as1 = (const float*)d_in[5];
    const float* ad1 = (const float*)d_in[6];
    const float* ae1 = (const float*)d_in[7];
    const float* b1  = (const float*)d_in[8];
    const float* W2  = (const float*)d_in[9];
    const float* We2 = (const float*)d_in[10];
    const float* as2 = (const float*)d_in[11];
    const float* ad2 = (const float*)d_in[12];
    const float* ae2 = (const float*)d_in[13];
    const float* b2  = (const float*)d_in[14];
    float* out = (float*)d_out;

    void *p_flag, *p_deg, *p_off, *p_scanv, *p_bsum, *p_slot,
         *p_pair, *p_alpha, *p_h, *p_h2, *p_x2,
         *p_ssrc, *p_sdst, *p_ssrc2, *p_sdst2;
    cudaGetSymbolAddress(&p_flag,  g_flag64);
    cudaGetSymbolAddress(&p_deg,   g_deg);
    cudaGetSymbolAddress(&p_off,   g_off);
    cudaGetSymbolAddress(&p_scanv, g_scanv);
    cudaGetSymbolAddress(&p_bsum,  g_bsum);
    cudaGetSymbolAddress(&p_slot,  g_slot);
    cudaGetSymbolAddress(&p_pair,  g_pair);
    cudaGetSymbolAddress(&p_alpha, g_alpha);
    cudaGetSymbolAddress(&p_h,     g_h);
    cudaGetSymbolAddress(&p_h2,    g_h2);
    cudaGetSymbolAddress(&p_x2,    g_x2);
    cudaGetSymbolAddress(&p_ssrc,  g_ssrc);
    cudaGetSymbolAddress(&p_sdst,  g_sdst);
    cudaGetSymbolAddress(&p_ssrc2, g_ssrc2);
    cudaGetSymbolAddress(&p_sdst2, g_sdst2);

    int*   flag  = (int*)p_flag;
    int*   deg   = (int*)p_deg;
    int*   off   = (int*)p_off;
    int*   scanv = (int*)p_scanv;
    int*   bsum  = (int*)p_bsum;
    int*   slot  = (int*)p_slot;
    int2*  pair  = (int2*)p_pair;
    float* alpha = (float*)p_alpha;
    float* h     = (float*)p_h;
    float* h2    = (float*)p_h2;
    float* x2    = (float*)p_x2;
    float* ssrc  = (float*)p_ssrc;
    float* sdst  = (float*)p_sdst;
    float* ssrc2 = (float*)p_ssrc2;
    float* sdst2 = (float*)p_sdst2;

    const int EB  = (EE + 255) / 256;
    const int EB4 = (EE / 4 + 255) / 256;
    const int GB  = (NN + GEMM_ROWS - 1) / GEMM_ROWS;
    const int WB  = (NN * 32 + 255) / 256;

    const int CH1 = NN - CH0;
    const int GB0 = CH0 / GEMM_ROWS;
    const int GB1 = (CH1 + GEMM_ROWS - 1) / GEMM_ROWS;
    const int WB0 = CH0 / 8;
    const int WB1 = (CH1 * 32 + 255) / 256;

    static cudaStream_t s2 = nullptr;
    static cudaEvent_t evFork = nullptr, evSide = nullptr, evA = nullptr, evB = nullptr;
    if (s2 == nullptr) {
        cudaStreamCreateWithFlags(&s2, cudaStreamNonBlocking);
        cudaEventCreateWithFlags(&evFork, cudaEventDisableTiming);
        cudaEventCreateWithFlags(&evSide, cudaEventDisableTiming);
        cudaEventCreateWithFlags(&evA,    cudaEventDisableTiming);
        cudaEventCreateWithFlags(&evB,    cudaEventDisableTiming);
    }

    // fork: side stream does layer-1 GEMM + dots while main builds CSR
    cudaEventRecord(evFork, 0);
    cudaStreamWaitEvent(s2, evFork, 0);

    gemm64_k<<<GB, 256, 0, s2>>>(x, W1, h, 0, NN);
    dots_k<<<WB, 256, 0, s2>>>(h, as1, ad1, ssrc, sdst, 0, NN);
    cudaEventRecord(evSide, s2);

    // main stream: CSR build
    detect_k<<<1, 32>>>(ei, flag);
    hist_k<<<EB4, 256>>>(ei, flag, deg, slot);
    scan1_k<<<NSB, SCAN_B>>>(deg, scanv, bsum);
    scan23_k<<<NSB, SCAN_B>>>(scanv, bsum, off);
    scatter_k<<<EB, 256>>>(ei, flag, ea, off, slot, pair);

    // join layer-1 prep, then race-free chunked pipeline
    cudaStreamWaitEvent(0, evSide, 0);

    agg_k<<<WB0, 256>>>(off, pair, h, ssrc, sdst, We1, ae1, b1, alpha, x2, 1, 0, CH0);
    cudaEventRecord(evA, 0);

    cudaStreamWaitEvent(s2, evA, 0);
    gemm64_k<<<GB0, 256, 0, s2>>>(x2, W2, h2, 0, CH0);
    dots_k<<<WB0, 256, 0, s2>>>(h2, as2, ad2, ssrc2, sdst2, 0, CH0);
    cudaEventRecord(evB, s2);

    agg_k<<<WB1, 256>>>(off, pair, h, ssrc, sdst, We1, ae1, b1, alpha, x2, 1, CH0, NN);
    gemm64_k<<<GB1, 256>>>(x2, W2, h2, CH0, NN);
    dots_k<<<WB1, 256>>>(h2, as2, ad2, ssrc2, sdst2, CH0, NN);

    cudaStreamWaitEvent(0, evB, 0);
    agg_k<<<WB, 256>>>(off, pair, h2, ssrc2, sdst2, We2, ae2, b2, alpha, out, 0, 0, NN);
}

// round 17
// speedup vs baseline: 1.1357x; 1.0208x over previous
#include <cuda_runtime.h>
#include <stdint.h>
#include <math.h>

#define NN 100000
#define EE 1600000
#define NEG_SLOPE 0.2f
#define SCAN_B 1024
#define NSB ((NN + SCAN_B - 1) / SCAN_B)   // 98 scan blocks
#define CH0 50048                          // 391 * 128 (chunk boundary, GEMM-tile aligned)

// ---------------- device scratch ----------------
__device__ int   g_flag64;
__device__ int   g_deg[NN];
__device__ int   g_off[NN + 1];
__device__ int   g_scanv[NN];
__device__ int   g_bsum[NSB];
__device__ int   g_slot[EE];
__device__ __align__(16) int2  g_pair[EE];   // (src, attr-bits): CSR, built once
__device__ __align__(16) int2  g_pair2[EE];  // (src, exp-bits): per-agg scratch
__device__ __align__(16) float g_h[(size_t)NN * 64];    // layer-1 features
__device__ __align__(16) float g_h2[(size_t)NN * 64];   // layer-2 features
__device__ __align__(16) float g_x2[(size_t)NN * 64];   // relu(layer-1 out)
__device__ float g_ssrc[NN],  g_sdst[NN];
__device__ float g_ssrc2[NN], g_sdst2[NN];

// ---------------- dtype detect ----------------
__global__ void detect_k(const void* __restrict__ ei, int* __restrict__ flag) {
    const long long* e64 = (const long long*)ei;
    int lane = threadIdx.x;
    long long a = e64[lane];
    long long b = e64[32 + lane];
    int bad = (a < 0 || a >= NN) || (b < 0 || b >= NN);
    unsigned bal = __ballot_sync(0xffffffffu, bad);
    if (lane == 0) *flag = (bal == 0) ? 1 : 0;
}

// ---------------- histogram over dst (4 edges/thread) + slot recording ----------------
__global__ void hist_k(const void* __restrict__ ei, const int* __restrict__ flag,
                       int* __restrict__ deg, int* __restrict__ slot) {
    int e = (blockIdx.x * blockDim.x + threadIdx.x) * 4;
    if (e >= EE) return;
    int d0, d1, d2, d3;
    if (*flag) {
        const long long* p = (const long long*)ei + EE + e;
        longlong2 a = ((const longlong2*)p)[0];
        longlong2 b = ((const longlong2*)p)[1];
        d0 = (int)a.x; d1 = (int)a.y; d2 = (int)b.x; d3 = (int)b.y;
    } else {
        int4 d = *(const int4*)((const int*)ei + EE + e);
        d0 = d.x; d1 = d.y; d2 = d.z; d3 = d.w;
    }
    int4 sl;
    sl.x = atomicAdd(deg + d0, 1);
    sl.y = atomicAdd(deg + d1, 1);
    sl.z = atomicAdd(deg + d2, 1);
    sl.w = atomicAdd(deg + d3, 1);
    *(int4*)(slot + e) = sl;
}

// ---------------- scan stage 1 (self-clearing) ----------------
__global__ void scan1_k(int* __restrict__ deg,
                        int* __restrict__ scanv, int* __restrict__ bsum) {
    __shared__ int s[SCAN_B];
    int tid = threadIdx.x;
    int i = blockIdx.x * SCAN_B + tid;
    int v = (i < NN) ? deg[i] : 0;
    s[tid] = v;
    if (i < NN) deg[i] = 0;
    __syncthreads();
#pragma unroll
    for (int d = 1; d < SCAN_B; d <<= 1) {
        int t = (tid >= d) ? s[tid - d] : 0;
        __syncthreads();
        s[tid] += t;
        __syncthreads();
    }
    if (i < NN) scanv[i] = s[tid];
    if (tid == SCAN_B - 1) bsum[blockIdx.x] = s[tid];
}

// ---------------- scan stage 2+3 fused ----------------
__global__ void scan23_k(const int* __restrict__ scanv, const int* __restrict__ bsum,
                         int* __restrict__ off) {
    __shared__ int s[128];
    int tid = threadIdx.x;
    if (tid < 128) s[tid] = (tid < NSB) ? bsum[tid] : 0;
    __syncthreads();
#pragma unroll
    for (int d = 1; d < 128; d <<= 1) {
        int t = (tid >= d && tid < 128) ? s[tid - d] : 0;
        __syncthreads();
        if (tid < 128) s[tid] += t;
        __syncthreads();
    }
    int bp = (blockIdx.x == 0) ? 0 : s[blockIdx.x - 1];
    int i = blockIdx.x * SCAN_B + tid;
    if (i < NN) off[i + 1] = scanv[i] + bp;
    if (i == 0) off[0] = 0;
}

// ---------------- scatter into packed CSR (atomic-free, ONE 8B store/edge) ----------------
__global__ void scatter_k(const void* __restrict__ ei, const int* __restrict__ flag,
                          const float* __restrict__ ea,
                          const int* __restrict__ off, const int* __restrict__ slot,
                          int2* __restrict__ pair) {
    int e = blockIdx.x * blockDim.x + threadIdx.x;
    if (e >= EE) return;
    int s, d;
    if (*flag) {
        const long long* p = (const long long*)ei;
        s = (int)p[e];
        d = (int)p[EE + e];
    } else {
        const int* p = (const int*)ei;
        s = p[e];
        d = p[EE + e];
    }
    int pos = off[d] + slot[e];
    int2 pr; pr.x = s; pr.y = __float_as_int(ea[e]);
    pair[pos] = pr;
}

// ---------------- GEMM: h = x @ W over row range [rowbase, rowend) ----------------
#define GEMM_ROWS 128
__global__ void __launch_bounds__(256, 2)
gemm64_k(const float* __restrict__ x, const float* __restrict__ W, float* __restrict__ h,
         int rowbase, int rowend) {
    __shared__ float4 xs[16][16];

    int tid = threadIdx.x;
    int d   = tid & 63;
    int y   = tid >> 6;

    float w[64];
#pragma unroll
    for (int k = 0; k < 64; ++k) w[k] = W[k * 64 + d];

    int row0 = rowbase + blockIdx.x * GEMM_ROWS;
#pragma unroll 1
    for (int t = 0; t < GEMM_ROWS / 16; ++t) {
        int rbase = row0 + t * 16;
        {
            int rr = rbase + (tid >> 4);
            float4 val = make_float4(0.f, 0.f, 0.f, 0.f);
            if (rr < rowend) val = ((const float4*)x)[(size_t)rr * 16 + (tid & 15)];
            xs[tid >> 4][tid & 15] = val;
        }
        __syncthreads();

        float acc0 = 0.f, acc1 = 0.f, acc2 = 0.f, acc3 = 0.f;
#pragma unroll
        for (int k4 = 0; k4 < 16; ++k4) {
            float w0 = w[4 * k4 + 0], w1 = w[4 * k4 + 1];
            float w2 = w[4 * k4 + 2], w3 = w[4 * k4 + 3];
            float4 a = xs[y * 4 + 0][k4];
            acc0 += a.x * w0 + a.y * w1 + a.z * w2 + a.w * w3;
            float4 b = xs[y * 4 + 1][k4];
            acc1 += b.x * w0 + b.y * w1 + b.z * w2 + b.w * w3;
            float4 c = xs[y * 4 + 2][k4];
            acc2 += c.x * w0 + c.y * w1 + c.z * w2 + c.w * w3;
            float4 e = xs[y * 4 + 3][k4];
            acc3 += e.x * w0 + e.y * w1 + e.z * w2 + e.w * w3;
        }
        int r0 = rbase + y * 4;
        if (r0 + 0 < rowend) h[(size_t)(r0 + 0) * 64 + d] = acc0;
        if (r0 + 1 < rowend) h[(size_t)(r0 + 1) * 64 + d] = acc1;
        if (r0 + 2 < rowend) h[(size_t)(r0 + 2) * 64 + d] = acc2;
        if (r0 + 3 < rowend) h[(size_t)(r0 + 3) * 64 + d] = acc3;
        __syncthreads();
    }
}

// ---------------- per-node attention dots over [nbase, nend) ----------------
__global__ void dots_k(const float* __restrict__ h,
                       const float* __restrict__ a_src, const float* __restrict__ a_dst,
                       float* __restrict__ ssrc, float* __restrict__ sdst,
                       int nbase, int nend) {
    int gt   = blockIdx.x * blockDim.x + threadIdx.x;
    int node = nbase + (gt >> 5);
    int lane = gt & 31;
    if (node >= nend) return;
    float h0 = h[(size_t)node * 64 + lane];
    float h1 = h[(size_t)node * 64 + 32 + lane];
    float ps = h0 * a_src[lane] + h1 * a_src[lane + 32];
    float pd = h0 * a_dst[lane] + h1 * a_dst[lane + 32];
#pragma unroll
    for (int o = 16; o; o >>= 1) {
        ps += __shfl_xor_sync(0xffffffffu, ps, o);
        pd += __shfl_xor_sync(0xffffffffu, pd, o);
    }
    if (lane == 0) { ssrc[node] = ps; sdst[node] = pd; }
}

// ---------------- warp-per-node aggregate (pass1 -> packed (u,e); pass2: 1 int4 / 2 edges) ----------------
__global__ void agg_k(const int* __restrict__ off,
                      const int2* __restrict__ pair,
                      int2* __restrict__ pair2,
                      const float* __restrict__ h,
                      const float* __restrict__ ssrc, const float* __restrict__ sdst,
                      const float* __restrict__ We, const float* __restrict__ ae,
                      const float* __restrict__ bias,
                      float* __restrict__ outp, int relu_out,
                      int vbase, int vend) {
    int gt   = blockIdx.x * blockDim.x + threadIdx.x;
    int lane = gt & 31;
    int v    = vbase + (gt >> 5);
    if (v >= vend) return;

    // c = sum_d We[d]*ae[d]
    float c = We[lane] * ae[lane] + We[lane + 32] * ae[lane + 32];
#pragma unroll
    for (int o = 16; o; o >>= 1) c += __shfl_xor_sync(0xffffffffu, c, o);

    int beg = off[v];
    int end = off[v + 1];
    float sdv = sdst[v];

    // pass 1: e = exp(leakyrelu(logit)) ; write (u, e) packed ; accumulate sum
    float s = 0.f;
    for (int j = beg + lane; j < end; j += 32) {
        int2 pr = pair[j];
        float a = ssrc[pr.x] + sdv + __int_as_float(pr.y) * c;
        a = (a > 0.f) ? a : NEG_SLOPE * a;
        float e = __expf(a);
        int2 p2; p2.x = pr.x; p2.y = __float_as_int(e);
        pair2[j] = p2;
        s += e;
    }
#pragma unroll
    for (int o = 16; o; o >>= 1) s += __shfl_xor_sync(0xffffffffu, s, o);
    float inv = 1.f / (s + 1e-16f);

    // pass 2: 2 edges per uniform int4 load; every weight scaled by inv at use
    float accx = 0.f, accy = 0.f;
    const float2* __restrict__ h2p = (const float2*)h;
    int j = beg;
    if ((j & 1) && j < end) {               // align to even index for 16B loads
        int2 pr = pair2[j];
        float w = __int_as_float(pr.y) * inv;
        float2 hv = h2p[(size_t)pr.x * 32 + lane];
        accx += w * hv.x; accy += w * hv.y;
        ++j;
    }
#pragma unroll 2
    for (; j + 1 < end; j += 2) {
        int4 pq = *(const int4*)(pair2 + j);   // (u0,e0,u1,e1), 16B-aligned (j even)
        float w0 = __int_as_float(pq.y) * inv;
        float w1 = __int_as_float(pq.w) * inv;
        float2 h0 = h2p[(size_t)pq.x * 32 + lane];
        float2 h1 = h2p[(size_t)pq.z * 32 + lane];
        accx += w0 * h0.x + w1 * h1.x;
        accy += w0 * h0.y + w1 * h1.y;
    }
    if (j < end) {
        int2 pr = pair2[j];
        float w = __int_as_float(pr.y) * inv;
        float2 hv = h2p[(size_t)pr.x * 32 + lane];
        accx += w * hv.x; accy += w * hv.y;
    }

    float2 b = ((const float2*)bias)[lane];
    float ox = accx + b.x;
    float oy = accy + b.y;
    if (relu_out) { ox = fmaxf(ox, 0.f); oy = fmaxf(oy, 0.f); }
    float2 o2; o2.x = ox; o2.y = oy;
    ((float2*)outp)[(size_t)v * 32 + lane] = o2;
}

// ---------------- launch ----------------
extern "C" void kernel_launch(void* const* d_in, const int* in_sizes, int n_in,
                              void* d_out, int out_size) {
    const float* x   = (const float*)d_in[0];
    const void*  ei  = d_in[1];
    const float* ea  = (const float*)d_in[2];
    const float* W1  = (const float*)d_in[3];
    const float* We1 = (const float*)d_in[4];
    const float* as1 = (const float*)d_in[5];
    const float* ad1 = (const float*)d_in[6];
    const float* ae1 = (const float*)d_in[7];
    const float* b1  = (const float*)d_in[8];
    const float* W2  = (const float*)d_in[9];
    const float* We2 = (const float*)d_in[10];
    const float* as2 = (const float*)d_in[11];
    const float* ad2 = (const float*)d_in[12];
    const float* ae2 = (const float*)d_in[13];
    const float* b2  = (const float*)d_in[14];
    float* out = (float*)d_out;

    void *p_flag, *p_deg, *p_off, *p_scanv, *p_bsum, *p_slot,
         *p_pair, *p_pair2, *p_h, *p_h2, *p_x2,
         *p_ssrc, *p_sdst, *p_ssrc2, *p_sdst2;
    cudaGetSymbolAddress(&p_flag,  g_flag64);
    cudaGetSymbolAddress(&p_deg,   g_deg);
    cudaGetSymbolAddress(&p_off,   g_off);
    cudaGetSymbolAddress(&p_scanv, g_scanv);
    cudaGetSymbolAddress(&p_bsum,  g_bsum);
    cudaGetSymbolAddress(&p_slot,  g_slot);
    cudaGetSymbolAddress(&p_pair,  g_pair);
    cudaGetSymbolAddress(&p_pair2, g_pair2);
    cudaGetSymbolAddress(&p_h,     g_h);
    cudaGetSymbolAddress(&p_h2,    g_h2);
    cudaGetSymbolAddress(&p_x2,    g_x2);
    cudaGetSymbolAddress(&p_ssrc,  g_ssrc);
    cudaGetSymbolAddress(&p_sdst,  g_sdst);
    cudaGetSymbolAddress(&p_ssrc2, g_ssrc2);
    cudaGetSymbolAddress(&p_sdst2, g_sdst2);

    int*   flag  = (int*)p_flag;
    int*   deg   = (int*)p_deg;
    int*   off   = (int*)p_off;
    int*   scanv = (int*)p_scanv;
    int*   bsum  = (int*)p_bsum;
    int*   slot  = (int*)p_slot;
    int2*  pair  = (int2*)p_pair;
    int2*  pair2 = (int2*)p_pair2;
    float* h     = (float*)p_h;
    float* h2    = (float*)p_h2;
    float* x2    = (float*)p_x2;
    float* ssrc  = (float*)p_ssrc;
    float* sdst  = (float*)p_sdst;
    float* ssrc2 = (float*)p_ssrc2;
    float* sdst2 = (float*)p_sdst2;

    const int EB  = (EE + 255) / 256;
    const int EB4 = (EE / 4 + 255) / 256;
    const int GB  = (NN + GEMM_ROWS - 1) / GEMM_ROWS;
    const int WB  = (NN * 32 + 255) / 256;

    const int CH1 = NN - CH0;
    const int GB0 = CH0 / GEMM_ROWS;
    const int GB1 = (CH1 + GEMM_ROWS - 1) / GEMM_ROWS;
    const int WB0 = CH0 / 8;
    const int WB1 = (CH1 * 32 + 255) / 256;

    static cudaStream_t s2 = nullptr;
    static cudaEvent_t evFork = nullptr, evSide = nullptr, evA = nullptr, evB = nullptr;
    if (s2 == nullptr) {
        cudaStreamCreateWithFlags(&s2, cudaStreamNonBlocking);
        cudaEventCreateWithFlags(&evFork, cudaEventDisableTiming);
        cudaEventCreateWithFlags(&evSide, cudaEventDisableTiming);
        cudaEventCreateWithFlags(&evA,    cudaEventDisableTiming);
        cudaEventCreateWithFlags(&evB,    cudaEventDisableTiming);
    }

    // fork: side stream does layer-1 GEMM + dots while main builds CSR
    cudaEventRecord(evFork, 0);
    cudaStreamWaitEvent(s2, evFork, 0);

    gemm64_k<<<GB, 256, 0, s2>>>(x, W1, h, 0, NN);
    dots_k<<<WB, 256, 0, s2>>>(h, as1, ad1, ssrc, sdst, 0, NN);
    cudaEventRecord(evSide, s2);

    // main stream: CSR build
    detect_k<<<1, 32>>>(ei, flag);
    hist_k<<<EB4, 256>>>(ei, flag, deg, slot);
    scan1_k<<<NSB, SCAN_B>>>(deg, scanv, bsum);
    scan23_k<<<NSB, SCAN_B>>>(scanv, bsum, off);
    scatter_k<<<EB, 256>>>(ei, flag, ea, off, slot, pair);

    // join layer-1 prep, then race-free chunked pipeline
    cudaStreamWaitEvent(0, evSide, 0);

    agg_k<<<WB0, 256>>>(off, pair, pair2, h, ssrc, sdst, We1, ae1, b1, x2, 1, 0, CH0);
    cudaEventRecord(evA, 0);

    cudaStreamWaitEvent(s2, evA, 0);
    gemm64_k<<<GB0, 256, 0, s2>>>(x2, W2, h2, 0, CH0);
    dots_k<<<WB0, 256, 0, s2>>>(h2, as2, ad2, ssrc2, sdst2, 0, CH0);
    cudaEventRecord(evB, s2);

    agg_k<<<WB1, 256>>>(off, pair, pair2, h, ssrc, sdst, We1, ae1, b1, x2, 1, CH0, NN);
    gemm64_k<<<GB1, 256>>>(x2, W2, h2, CH0, NN);
    dots_k<<<WB1, 256>>>(h2, as2, ad2, ssrc2, sdst2, CH0, NN);

    cudaStreamWaitEvent(0, evB, 0);
    agg_k<<<WB, 256>>>(off, pair, pair2, h2, ssrc2, sdst2, We2, ae2, b2, out, 0, 0, NN);
}